// round 6
// baseline (speedup 1.0000x reference)
#include <cuda_runtime.h>
#include <cstdint>

// Problem constants
#define NN 16      // N (both u and v)
#define CC 4       // C
#define HH 32
#define WW 32
#define SS 1024    // H*W
#define K2 9       // 3x3
#define EE 144     // C*C*K2 floats per (u,v,s) chunk
#define ST 32      // s-values per block
#define NLANES 36  // EE/4 quads
#define NSGRP 8    // s-groups (each handles 4 s)
#define NTHREADS (NSGRP * NLANES)  // 288

#define STAGE_BYTES (ST * EE * 4)          // 18432
#define SMEM_W 0                            // 2 stages of weight
#define SMEM_X (2 * STAGE_BYTES)            // 2 stages of xu
#define SMEM_CM (4 * STAGE_BYTES)           // 73728: cm [16 u][16 co]
#define SMEM_MBAR (SMEM_CM + 1024)          // 74752: full[2] mbarriers
#define SMEM_TOTAL (SMEM_MBAR + 32)         // 74784

// xu scratch: [u][s][p=144] o-replicated unfold of x (9.4 MB).
// MUST be 16B-aligned for cp.async.bulk sources.
__device__ __align__(128) float xu_g[NN * SS * EE];

// ---- packed f32x2 helpers ----
__device__ __forceinline__ unsigned long long ffma2(unsigned long long a,
                                                    unsigned long long b,
                                                    unsigned long long c) {
    unsigned long long d;
    asm("fma.rn.f32x2 %0, %1, %2, %3;" : "=l"(d) : "l"(a), "l"(b), "l"(c));
    return d;
}
__device__ __forceinline__ unsigned long long fmul2(unsigned long long a,
                                                    unsigned long long b) {
    unsigned long long d;
    asm("mul.rn.f32x2 %0, %1, %2;" : "=l"(d) : "l"(a), "l"(b));
    return d;
}
__device__ __forceinline__ unsigned long long pack2(float lo, float hi) {
    unsigned long long d;
    asm("mov.b64 %0, {%1, %2};" : "=l"(d) : "f"(lo), "f"(hi));
    return d;
}
__device__ __forceinline__ unsigned smem_u32(const void* p) {
    unsigned a;
    asm("{ .reg .u64 t; cvta.to.shared.u64 t, %1; cvt.u32.u64 %0, t; }"
        : "=r"(a) : "l"(p));
    return a;
}

// ---- mbarrier helpers ----
__device__ __forceinline__ void mbar_init(unsigned mb, unsigned count) {
    asm volatile("mbarrier.init.shared.b64 [%0], %1;" :: "r"(mb), "r"(count) : "memory");
}
__device__ __forceinline__ void mbar_expect_tx(unsigned mb, unsigned bytes) {
    asm volatile("mbarrier.arrive.expect_tx.shared.b64 _, [%0], %1;"
                 :: "r"(mb), "r"(bytes) : "memory");
}
__device__ __forceinline__ void mbar_wait(unsigned mb, unsigned parity) {
    unsigned done;
    asm volatile(
        "{\n\t.reg .pred p;\n\t"
        "mbarrier.try_wait.parity.acquire.cta.shared::cta.b64 p, [%1], %2;\n\t"
        "selp.b32 %0, 1, 0, p;\n\t}"
        : "=r"(done) : "r"(mb), "r"(parity) : "memory");
    if (!done) {
        asm volatile(
            "{\n\t.reg .pred P1;\n\t"
            "W_%=:\n\t"
            "mbarrier.try_wait.parity.acquire.cta.shared::cta.b64 P1, [%0], %1, 0x989680;\n\t"
            "@P1 bra.uni D_%=;\n\t"
            "bra.uni W_%=;\n\t"
            "D_%=:\n\t}"
            :: "r"(mb), "r"(parity) : "memory");
    }
}
__device__ __forceinline__ void bulk_copy(unsigned dst_smem, const void* src,
                                          unsigned bytes, unsigned mb) {
    asm volatile(
        "cp.async.bulk.shared::cta.global.mbarrier::complete_tx::bytes [%0], [%1], %2, [%3];"
        :: "r"(dst_smem), "l"(src), "r"(bytes), "r"(mb) : "memory");
}

// ======================= kernel 1: build xu scratch =======================
__global__ __launch_bounds__(256)
void build_xu_kernel(const float* __restrict__ x) {
    int idx = blockIdx.x * 256 + threadIdx.x;     // over 16*1024*36 quads
    if (idx >= NN * SS * NLANES) return;
    int q = idx % NLANES;
    int s = (idx / NLANES) % SS;
    int u = idx / (NLANES * SS);
    int h = s >> 5, w = s & 31;
    float4 v;
    float* vp = (float*)&v;
#pragma unroll
    for (int e = 0; e < 4; e++) {
        int p  = q * 4 + e;
        int c  = p / 36;
        int k  = p % 9;            // p = c*36 + o*9 + k
        int ki = k / 3, kj = k % 3;
        int y  = h + ki - 1, xx = w + kj - 1;
        float val = 0.0f;
        if ((unsigned)y < 32u && (unsigned)xx < 32u)
            val = x[((u * CC + c) * HH + y) * WW + xx];
        vp[e] = val;
    }
    *(float4*)&xu_g[(size_t)idx * 4] = v;
}

// ======================= kernel 2: main pipeline ==========================
__global__ __launch_bounds__(NTHREADS)
void plastic_edges_kernel(const float* __restrict__ weight,
                          const float* __restrict__ chan_map,
                          const float* __restrict__ mask,
                          float* __restrict__ out) {
    extern __shared__ __align__(128) char smem[];
    float* cm_sh = (float*)(smem + SMEM_CM);       // [16 u][16 co]
    const unsigned sbase = smem_u32(smem);
    const unsigned mb_full0 = sbase + SMEM_MBAR;
    const unsigned mb_full1 = sbase + SMEM_MBAR + 8;

    const int t    = threadIdx.x;
    const int bs0  = blockIdx.x * ST;      // s tile base
    const int v    = blockIdx.y;           // one v per block
    const int sgrp = t / NLANES;           // 0..7
    const int lane = t % NLANES;           // 0..35 (quad index)

    // ---- stage cm_sh[u][c*4+o] ----
    if (t < 256) {
        int u  = t >> 4;
        int co = t & 15;
        int uv = u * NN + v;
        cm_sh[t] = chan_map[uv * 16 + co] * mask[uv];
    }

    if (t == 0) {
        mbar_init(mb_full0, 1);
        mbar_init(mb_full1, 1);
    }
    __syncthreads();

    const float* wsrc0 = weight + ((size_t)v * SS + bs0) * EE;  // + u*NN*SS*EE
    const float* xsrc0 = xu_g + (size_t)bs0 * EE;               // + u*SS*EE
    const size_t wstride = (size_t)NN * SS * EE;
    const size_t xstride = (size_t)SS * EE;

    // prologue: fill stages for u=0, u=1
    if (t == 0) {
#pragma unroll
        for (int u = 0; u < 2; u++) {
            unsigned mb = (u & 1) ? mb_full1 : mb_full0;
            mbar_expect_tx(mb, 2 * STAGE_BYTES);
            bulk_copy(sbase + SMEM_W + (u & 1) * STAGE_BYTES,
                      wsrc0 + (size_t)u * wstride, STAGE_BYTES, mb);
            bulk_copy(sbase + SMEM_X + (u & 1) * STAGE_BYTES,
                      xsrc0 + (size_t)u * xstride, STAGE_BYTES, mb);
        }
    }

    // per-thread cm gather indices for this quad (p = lane*4 + e)
    int cmi[4];
#pragma unroll
    for (int e = 0; e < 4; e++) {
        int p  = lane * 4 + e;
        int c  = p / 36;
        int o  = (p % 36) / 9;
        cmi[e] = c * 4 + o;
    }

    unsigned long long acc[4][2];
#pragma unroll
    for (int i = 0; i < 4; i++) { acc[i][0] = 0ull; acc[i][1] = 0ull; }

    const unsigned lane_off = lane * 16;                    // bytes
    const unsigned sl0_off  = (sgrp * 4) * (EE * 4);        // bytes

    for (int u = 0; u < NN; u++) {
        const int slot = u & 1;
        const unsigned mb = slot ? mb_full1 : mb_full0;
        mbar_wait(mb, (u >> 1) & 1);

        const float* cmb = &cm_sh[u * 16];
        unsigned long long cm01 = pack2(cmb[cmi[0]], cmb[cmi[1]]);
        unsigned long long cm23 = pack2(cmb[cmi[2]], cmb[cmi[3]]);
        unsigned sw = sbase + SMEM_W + slot * STAGE_BYTES + sl0_off + lane_off;
        unsigned sx = sbase + SMEM_X + slot * STAGE_BYTES + sl0_off + lane_off;
#pragma unroll
        for (int i = 0; i < 4; i++) {
            unsigned long long w01, w23, x01, x23;
            asm volatile("ld.shared.v2.b64 {%0,%1}, [%2];"
                : "=l"(w01), "=l"(w23) : "r"(sw + i * (EE * 4)));
            asm volatile("ld.shared.v2.b64 {%0,%1}, [%2];"
                : "=l"(x01), "=l"(x23) : "r"(sx + i * (EE * 4)));
            acc[i][0] = ffma2(w01, fmul2(x01, cm01), acc[i][0]);
            acc[i][1] = ffma2(w23, fmul2(x23, cm23), acc[i][1]);
        }
        __syncthreads();   // all reads of this slot done
        if (t == 0 && u + 2 < NN) {
            mbar_expect_tx(mb, 2 * STAGE_BYTES);
            bulk_copy(sbase + SMEM_W + slot * STAGE_BYTES,
                      wsrc0 + (size_t)(u + 2) * wstride, STAGE_BYTES, mb);
            bulk_copy(sbase + SMEM_X + slot * STAGE_BYTES,
                      xsrc0 + (size_t)(u + 2) * xstride, STAGE_BYTES, mb);
        }
    }

    // ---- c-reduction via shared (reuse stage buffers), fused fold scatter ----
    float* red = (float*)smem;   // [32 s][144]  = 18432 B, fits in stage-w area
#pragma unroll
    for (int i = 0; i < 4; i++) {
        ulonglong2 pk; pk.x = acc[i][0]; pk.y = acc[i][1];
        *(ulonglong2*)&red[(sgrp * 4 + i) * EE + lane * 4] = pk;
    }
    __syncthreads();

    // 32*36 = 1152 (s, o*9+k) outputs; sum 4 c-slices each; fold-scatter
    for (int r = t; r < ST * 36; r += NTHREADS) {
        int sl = r / 36;
        int ok = r % 36;             // o*9 + k
        int o  = ok / 9, k = ok % 9;
        const float* rb = &red[sl * EE + ok];
        float val = rb[0] + rb[36] + rb[72] + rb[108];
        // fold: channel index ch = k*C + o decoded as (cf, fi, fj)
        int ch  = k * CC + o;
        int cf  = ch / 9;
        int rem = ch % 9;
        int fi  = rem / 3, fj = rem % 3;
        int s = bs0 + sl;
        int h = s >> 5, w = s & 31;
        int y = h + fi - 1, xx = w + fj - 1;
        if ((unsigned)y < 32u && (unsigned)xx < 32u)
            atomicAdd(&out[((v * CC + cf) * HH + y) * WW + xx], val);
    }
}

extern "C" void kernel_launch(void* const* d_in, const int* in_sizes, int n_in,
                              void* d_out, int out_size) {
    // identify inputs by element count (robust to ordering)
    const float *x = nullptr, *wt = nullptr, *cm = nullptr, *mk = nullptr;
    for (int i = 0; i < n_in; i++) {
        switch (in_sizes[i]) {
            case NN * CC * HH * WW:           x  = (const float*)d_in[i]; break; // 65536
            case NN * NN * SS * CC * CC * K2: wt = (const float*)d_in[i]; break; // 37748736
            case NN * NN * CC * CC:           cm = (const float*)d_in[i]; break; // 4096
            case NN * NN:                     mk = (const float*)d_in[i]; break; // 256
            default: break;
        }
    }
    float* out = (float*)d_out;

    cudaFuncSetAttribute(plastic_edges_kernel,
                         cudaFuncAttributeMaxDynamicSharedMemorySize, SMEM_TOTAL);

    cudaMemsetAsync(out, 0, (size_t)out_size * sizeof(float), 0);

    // build xu scratch (o-replicated unfold), then stream
    int nq = NN * SS * NLANES;                       // 589824 quads
    build_xu_kernel<<<(nq + 255) / 256, 256>>>(x);

    dim3 grid(SS / ST, NN);                          // (32, 16) = 512 blocks
    plastic_edges_kernel<<<grid, NTHREADS, SMEM_TOTAL, 0>>>(wt, cm, mk, out);
}

// round 7
// speedup vs baseline: 1.3794x; 1.3794x over previous
#include <cuda_runtime.h>
#include <cstdint>

// Problem constants
#define NN 16      // N (both u and v)
#define CC 4       // C
#define HH 32
#define WW 32
#define SS 1024    // H*W
#define K2 9       // 3x3
#define EE 144     // C*C*K2 floats per (u,v,s) chunk
#define ST 32      // s-values per block = one image row
#define NLANES 36  // EE/4 quads
#define NSGRP 8    // s-groups (each handles 4 s)
#define NTHREADS (NSGRP * NLANES)  // 288
#define NSTAGE 4   // weight pipeline depth

#define STAGE_BYTES (ST * EE * 4)              // 18432
// x smem tile: [u(16)][c(4)][row(3)][col(36: 0..33 used, 0 & 33 zero guards)]
#define XS_FLOATS (NN * CC * 3 * 36)           // 6912
#define SMEM_W 0                               // 4 weight stages
#define SMEM_XS (NSTAGE * STAGE_BYTES)         // 73728
#define SMEM_CM (SMEM_XS + XS_FLOATS * 4)      // 101376: cm [16 u][16 co]
#define SMEM_MBAR (SMEM_CM + 1024)             // 102400
#define SMEM_TOTAL (SMEM_MBAR + 64)            // 102464

__device__ __forceinline__ unsigned smem_u32(const void* p) {
    unsigned a;
    asm("{ .reg .u64 t; cvta.to.shared.u64 t, %1; cvt.u32.u64 %0, t; }"
        : "=r"(a) : "l"(p));
    return a;
}

// ---- mbarrier helpers ----
__device__ __forceinline__ void mbar_init(unsigned mb, unsigned count) {
    asm volatile("mbarrier.init.shared.b64 [%0], %1;" :: "r"(mb), "r"(count) : "memory");
}
__device__ __forceinline__ void mbar_expect_tx(unsigned mb, unsigned bytes) {
    asm volatile("mbarrier.arrive.expect_tx.shared.b64 _, [%0], %1;"
                 :: "r"(mb), "r"(bytes) : "memory");
}
__device__ __forceinline__ void mbar_wait(unsigned mb, unsigned parity) {
    unsigned done;
    asm volatile(
        "{\n\t.reg .pred p;\n\t"
        "mbarrier.try_wait.parity.acquire.cta.shared::cta.b64 p, [%1], %2;\n\t"
        "selp.b32 %0, 1, 0, p;\n\t}"
        : "=r"(done) : "r"(mb), "r"(parity) : "memory");
    if (!done) {
        asm volatile(
            "{\n\t.reg .pred P1;\n\t"
            "W_%=:\n\t"
            "mbarrier.try_wait.parity.acquire.cta.shared::cta.b64 P1, [%0], %1, 0x989680;\n\t"
            "@P1 bra.uni D_%=;\n\t"
            "bra.uni W_%=;\n\t"
            "D_%=:\n\t}"
            :: "r"(mb), "r"(parity) : "memory");
    }
}
__device__ __forceinline__ void bulk_copy(unsigned dst_smem, const void* src,
                                          unsigned bytes, unsigned mb) {
    asm volatile(
        "cp.async.bulk.shared::cta.global.mbarrier::complete_tx::bytes [%0], [%1], %2, [%3];"
        :: "r"(dst_smem), "l"(src), "r"(bytes), "r"(mb) : "memory");
}

__global__ __launch_bounds__(NTHREADS)
void plastic_edges_kernel(const float* __restrict__ x,
                          const float* __restrict__ weight,
                          const float* __restrict__ chan_map,
                          const float* __restrict__ mask,
                          float* __restrict__ out) {
    extern __shared__ __align__(128) char smem[];
    float* xs    = (float*)(smem + SMEM_XS);   // [u][c][3][36]
    float* cm_sh = (float*)(smem + SMEM_CM);   // [16 u][16 co]
    const unsigned sbase = smem_u32(smem);

    const int t    = threadIdx.x;
    const int bs0  = blockIdx.x * ST;      // s tile base (one row: h = blockIdx.x)
    const int h    = blockIdx.x;
    const int v    = blockIdx.y;           // one v per block
    const int sgrp = t / NLANES;           // 0..7
    const int lane = t % NLANES;           // 0..35 (quad index)

    // ---- mbarriers ----
    if (t == 0) {
#pragma unroll
        for (int s = 0; s < NSTAGE; s++) mbar_init(sbase + SMEM_MBAR + 8 * s, 1);
    }
    // ---- stage cm_sh[u][c*4+o] ----
    if (t < 256) {
        int u  = t >> 4;
        int co = t & 15;
        int uv = u * NN + v;
        cm_sh[t] = chan_map[uv * 16 + co] * mask[uv];
    }
    __syncthreads();   // mbarrier init visible before TMA arms

    const float* wsrc0 = weight + ((size_t)v * SS + bs0) * EE;  // + u*NN*SS*EE
    const size_t wstride = (size_t)NN * SS * EE;

    // prologue: arm + fill stages for u=0..3
    if (t == 0) {
#pragma unroll
        for (int u = 0; u < NSTAGE; u++) {
            unsigned mb = sbase + SMEM_MBAR + 8 * u;
            mbar_expect_tx(mb, STAGE_BYTES);
            bulk_copy(sbase + SMEM_W + u * STAGE_BYTES,
                      wsrc0 + (size_t)u * wstride, STAGE_BYTES, mb);
        }
    }

    // ---- stage raw x rows into xs (overlaps with TMA fills) ----
    // zero-init (guard cols + invalid halo rows), then fill interior
    for (int i = t; i < XS_FLOATS; i += NTHREADS) xs[i] = 0.0f;
    __syncthreads();
    for (int i = t; i < NN * CC * 3 * 32; i += NTHREADS) {
        int w  = i & 31;
        int rr = (i >> 5) % 3;             // 0..2 -> rows h-1..h+1
        int uc = i / 96;                   // u*4 + c
        int r  = h + rr - 1;
        if ((unsigned)r < 32u)
            xs[(uc * 3 + rr) * 36 + 1 + w] = x[(uc * 32 + r) * 32 + w];
    }

    // per-thread static decode for quad p = lane*4 + e
    // x value for p: xs[u][c][ki][ (w + kj - 1) + 1 ],  w = sgrp*4 + i
    int cmi[4];     // cm index c*4+o
    unsigned xoff[4];  // byte offset within a u-slab, minus the i term
    {
        int p0 = lane * 4;
        int c  = p0 / 36;
#pragma unroll
        for (int e = 0; e < 4; e++) {
            int p  = p0 + e;
            int o  = (p % 36) / 9;
            int k  = p % 9;
            int ki = k / 3, kj = k % 3;
            cmi[e]  = c * 4 + o;
            xoff[e] = ((unsigned)((c * 3 + ki) * 36 + (sgrp * 4) + kj)) * 4u;
        }
    }
    const unsigned xb = sbase + SMEM_XS;   // xs base (u stride = 432 floats = 1728 B)

    float acc[4][4];
#pragma unroll
    for (int i = 0; i < 4; i++)
#pragma unroll
        for (int e = 0; e < 4; e++) acc[i][e] = 0.0f;

    const unsigned wthr = (unsigned)(sgrp * 4) * (EE * 4) + (unsigned)lane * 16;

    __syncthreads();   // xs fully staged

    for (int u = 0; u < NN; u++) {
        const int slot = u & (NSTAGE - 1);
        const unsigned mb = sbase + SMEM_MBAR + 8 * slot;
        mbar_wait(mb, (u >> 2) & 1);

        float cmv[4];
#pragma unroll
        for (int e = 0; e < 4; e++) cmv[e] = cm_sh[u * 16 + cmi[e]];

        const unsigned sw = sbase + SMEM_W + slot * STAGE_BYTES + wthr;
        const unsigned xu = xb + (unsigned)u * 1728u;
#pragma unroll
        for (int i = 0; i < 4; i++) {
            float w0, w1, w2, w3;
            asm volatile("ld.shared.v4.f32 {%0,%1,%2,%3}, [%4];"
                : "=f"(w0), "=f"(w1), "=f"(w2), "=f"(w3) : "r"(sw + i * (EE * 4)));
            float xv[4];
#pragma unroll
            for (int e = 0; e < 4; e++) {
                asm volatile("ld.shared.f32 %0, [%1];"
                    : "=f"(xv[e]) : "r"(xu + xoff[e] + (unsigned)(i * 4)));
            }
            acc[i][0] = fmaf(w0, xv[0] * cmv[0], acc[i][0]);
            acc[i][1] = fmaf(w1, xv[1] * cmv[1], acc[i][1]);
            acc[i][2] = fmaf(w2, xv[2] * cmv[2], acc[i][2]);
            acc[i][3] = fmaf(w3, xv[3] * cmv[3], acc[i][3]);
        }
        __syncthreads();   // all reads of this slot done
        if (t == 0 && u + NSTAGE < NN) {
            mbar_expect_tx(mb, STAGE_BYTES);
            bulk_copy(sbase + SMEM_W + slot * STAGE_BYTES,
                      wsrc0 + (size_t)(u + NSTAGE) * wstride, STAGE_BYTES, mb);
        }
    }

    // ---- c-reduction via shared (reuse stage-0 buffer), fused fold scatter ----
    // slot 0's last copy (for u=12) was consumed at u=12; no copy in flight.
    float* red = (float*)smem;   // [32 s][144] = 18432 B
#pragma unroll
    for (int i = 0; i < 4; i++) {
        float4 pk = make_float4(acc[i][0], acc[i][1], acc[i][2], acc[i][3]);
        *(float4*)&red[(sgrp * 4 + i) * EE + lane * 4] = pk;
    }
    __syncthreads();

    // 32*36 = 1152 (s, o*9+k) outputs; sum 4 c-slices each; fold-scatter
    for (int r = t; r < ST * 36; r += NTHREADS) {
        int sl = r / 36;
        int ok = r % 36;             // o*9 + k
        int o  = ok / 9, k = ok % 9;
        const float* rb = &red[sl * EE + ok];
        float val = rb[0] + rb[36] + rb[72] + rb[108];
        // fold: channel index ch = k*C + o decoded as (cf, fi, fj)
        int ch  = k * CC + o;
        int cf  = ch / 9;
        int rem = ch % 9;
        int fi  = rem / 3, fj = rem % 3;
        int s = bs0 + sl;
        int hh = s >> 5, w = s & 31;
        int y = hh + fi - 1, xx = w + fj - 1;
        if ((unsigned)y < 32u && (unsigned)xx < 32u)
            atomicAdd(&out[((v * CC + cf) * HH + y) * WW + xx], val);
    }
}

extern "C" void kernel_launch(void* const* d_in, const int* in_sizes, int n_in,
                              void* d_out, int out_size) {
    // identify inputs by element count (robust to ordering)
    const float *x = nullptr, *wt = nullptr, *cm = nullptr, *mk = nullptr;
    for (int i = 0; i < n_in; i++) {
        switch (in_sizes[i]) {
            case NN * CC * HH * WW:           x  = (const float*)d_in[i]; break; // 65536
            case NN * NN * SS * CC * CC * K2: wt = (const float*)d_in[i]; break; // 37748736
            case NN * NN * CC * CC:           cm = (const float*)d_in[i]; break; // 4096
            case NN * NN:                     mk = (const float*)d_in[i]; break; // 256
            default: break;
        }
    }
    float* out = (float*)d_out;

    cudaFuncSetAttribute(plastic_edges_kernel,
                         cudaFuncAttributeMaxDynamicSharedMemorySize, SMEM_TOTAL);

    cudaMemsetAsync(out, 0, (size_t)out_size * sizeof(float), 0);

    dim3 grid(SS / ST, NN);                  // (32, 16) = 512 blocks
    plastic_edges_kernel<<<grid, NTHREADS, SMEM_TOTAL, 0>>>(x, wt, cm, mk, out);
}

// round 10
// speedup vs baseline: 1.4439x; 1.0468x over previous
#include <cuda_runtime.h>
#include <cstdint>

// Problem constants
#define NN 16      // N (both u and v)
#define CC 4       // C
#define HH 32
#define WW 32
#define SS 1024    // H*W
#define K2 9       // 3x3
#define EE 144     // C*C*K2 floats per (u,v,s) chunk
#define ST 16      // s-values per block = half an image row
#define NLANES 36  // EE/4 quads
#define NSGRP 8    // s-groups (each handles 2 s)
#define NTHREADS (NSGRP * NLANES)  // 288
#define NSTAGE 4   // weight pipeline depth

#define STAGE_BYTES (ST * EE * 4)              // 9216
// x smem tile: [u(16)][c(4)][row(3)][col(20: j=0..17 used = gcols w0-1..w0+16)]
#define XS_FLOATS (NN * CC * 3 * 20)           // 3840
#define SMEM_W 0                               // 4 weight stages (36864 B)
#define SMEM_XS (NSTAGE * STAGE_BYTES)         // 36864
#define SMEM_CM (SMEM_XS + XS_FLOATS * 4)      // 52224: cm [16 u][16 co]
#define SMEM_MBAR (SMEM_CM + 1024)             // 53248: full[4]
#define SMEM_TOTAL (SMEM_MBAR + 64)            // 53312

__device__ __forceinline__ unsigned smem_u32(const void* p) {
    unsigned a;
    asm("{ .reg .u64 t; cvta.to.shared.u64 t, %1; cvt.u32.u64 %0, t; }"
        : "=r"(a) : "l"(p));
    return a;
}

// ---- mbarrier helpers ----
__device__ __forceinline__ void mbar_init(unsigned mb, unsigned count) {
    asm volatile("mbarrier.init.shared.b64 [%0], %1;" :: "r"(mb), "r"(count) : "memory");
}
__device__ __forceinline__ void mbar_expect_tx(unsigned mb, unsigned bytes) {
    asm volatile("mbarrier.arrive.expect_tx.shared.b64 _, [%0], %1;"
                 :: "r"(mb), "r"(bytes) : "memory");
}
__device__ __forceinline__ void mbar_wait(unsigned mb, unsigned parity) {
    unsigned done;
    asm volatile(
        "{\n\t.reg .pred p;\n\t"
        "mbarrier.try_wait.parity.acquire.cta.shared::cta.b64 p, [%1], %2;\n\t"
        "selp.b32 %0, 1, 0, p;\n\t}"
        : "=r"(done) : "r"(mb), "r"(parity) : "memory");
    if (!done) {
        asm volatile(
            "{\n\t.reg .pred P1;\n\t"
            "W_%=:\n\t"
            "mbarrier.try_wait.parity.acquire.cta.shared::cta.b64 P1, [%0], %1, 0x989680;\n\t"
            "@P1 bra.uni D_%=;\n\t"
            "bra.uni W_%=;\n\t"
            "D_%=:\n\t}"
            :: "r"(mb), "r"(parity) : "memory");
    }
}
__device__ __forceinline__ void bulk_copy(unsigned dst_smem, const void* src,
                                          unsigned bytes, unsigned mb) {
    asm volatile(
        "cp.async.bulk.shared::cta.global.mbarrier::complete_tx::bytes [%0], [%1], %2, [%3];"
        :: "r"(dst_smem), "l"(src), "r"(bytes), "r"(mb) : "memory");
}

__global__ __launch_bounds__(NTHREADS, 4)
void plastic_edges_kernel(const float* __restrict__ x,
                          const float* __restrict__ weight,
                          const float* __restrict__ chan_map,
                          const float* __restrict__ mask,
                          float* __restrict__ out) {
    extern __shared__ __align__(128) char smem[];
    float* xs    = (float*)(smem + SMEM_XS);   // [u][c][3][20]
    float* cm_sh = (float*)(smem + SMEM_CM);   // [16 u][16 co]
    const unsigned sbase = smem_u32(smem);
    const unsigned mbF = sbase + SMEM_MBAR;    // full[4]

    const int t    = threadIdx.x;
    const int bx   = blockIdx.x;           // 0..63
    const int h    = bx >> 1;
    const int w0   = (bx & 1) << 4;
    const int bs0  = h * 32 + w0;          // s tile base
    const int v    = blockIdx.y;           // one v per block
    const int sgrp = t / NLANES;           // 0..7
    const int lane = t % NLANES;           // 0..35 (quad index)

    // ---- mbarriers ----
    if (t == 0) {
#pragma unroll
        for (int s = 0; s < NSTAGE; s++) mbar_init(mbF + 8 * s, 1);
    }
    // ---- stage cm_sh[u][c*4+o] ----
    if (t < 256) {
        int u  = t >> 4;
        int co = t & 15;
        int uv = u * NN + v;
        cm_sh[t] = chan_map[uv * 16 + co] * mask[uv];
    }
    __syncthreads();   // mbarrier init visible before TMA arms

    const float* wsrc0 = weight + ((size_t)v * SS + bs0) * EE;  // + u*NN*SS*EE
    const size_t wstride = (size_t)NN * SS * EE;

    // prologue: arm + fill stages for u=0..3
    if (t == 0) {
#pragma unroll
        for (int u = 0; u < NSTAGE; u++) {
            mbar_expect_tx(mbF + 8 * u, STAGE_BYTES);
            bulk_copy(sbase + SMEM_W + u * STAGE_BYTES,
                      wsrc0 + (size_t)u * wstride, STAGE_BYTES, mbF + 8 * u);
        }
    }

    // ---- stage raw x rows into xs (overlaps with TMA fills) ----
    for (int i = t; i < XS_FLOATS; i += NTHREADS) xs[i] = 0.0f;
    __syncthreads();
    for (int i = t; i < NN * CC * 3 * 18; i += NTHREADS) {
        int j  = i % 18;                   // local col 0..17 -> gcol w0-1+j
        int rr = (i / 18) % 3;             // rows h-1..h+1
        int uc = i / 54;                   // u*4 + c
        int r  = h + rr - 1;
        int gc = w0 - 1 + j;
        if ((unsigned)r < 32u && (unsigned)gc < 32u)
            xs[(uc * 3 + rr) * 20 + j] = x[(uc * 32 + r) * 32 + gc];
    }

    // per-thread static decode for quad p = lane*4 + e
    // x value for (p, sl): xs[u][c][ki][ sl + kj ]   (sl = local s = local w)
    int cmi[4];        // cm index c*4+o
    unsigned xoff[4];  // byte offset within a u-slab, excluding sl
    {
        int p0 = lane * 4;
        int c  = p0 / 36;                  // constant across the quad
#pragma unroll
        for (int e = 0; e < 4; e++) {
            int p  = p0 + e;
            int o  = (p % 36) / 9;
            int k  = p % 9;
            int ki = k / 3, kj = k % 3;
            cmi[e]  = c * 4 + o;
            xoff[e] = ((unsigned)((c * 3 + ki) * 20 + kj)) * 4u;
        }
    }
    const unsigned xb = sbase + SMEM_XS;   // u stride = 4*3*20*4 = 960 B

    float acc[2][4];
#pragma unroll
    for (int i = 0; i < 2; i++)
#pragma unroll
        for (int e = 0; e < 4; e++) acc[i][e] = 0.0f;

    const unsigned wthr = (unsigned)(sgrp * 2) * (EE * 4) + (unsigned)lane * 16;

    __syncthreads();   // xs fully staged

    for (int u = 0; u < NN; u++) {
        const int slot = u & (NSTAGE - 1);
        const unsigned par = (u >> 2) & 1;
        mbar_wait(mbF + 8 * slot, par);

        float cmv[4];
#pragma unroll
        for (int e = 0; e < 4; e++) cmv[e] = cm_sh[u * 16 + cmi[e]];

        const unsigned sw = sbase + SMEM_W + slot * STAGE_BYTES + wthr;
        const unsigned xu = xb + (unsigned)u * 960u;
#pragma unroll
        for (int i = 0; i < 2; i++) {
            const unsigned sl = (unsigned)(sgrp * 2 + i);
            float w0v, w1v, w2v, w3v;
            asm volatile("ld.shared.v4.f32 {%0,%1,%2,%3}, [%4];"
                : "=f"(w0v), "=f"(w1v), "=f"(w2v), "=f"(w3v)
                : "r"(sw + i * (EE * 4)));
            float xv[4];
#pragma unroll
            for (int e = 0; e < 4; e++) {
                asm volatile("ld.shared.f32 %0, [%1];"
                    : "=f"(xv[e]) : "r"(xu + xoff[e] + sl * 4u));
            }
            acc[i][0] = fmaf(w0v, xv[0] * cmv[0], acc[i][0]);
            acc[i][1] = fmaf(w1v, xv[1] * cmv[1], acc[i][1]);
            acc[i][2] = fmaf(w2v, xv[2] * cmv[2], acc[i][2]);
            acc[i][3] = fmaf(w3v, xv[3] * cmv[3], acc[i][3]);
        }
        __syncthreads();   // all reads of this slot done (proven-safe release)
        if (t == 0 && u + NSTAGE < NN) {
            mbar_expect_tx(mbF + 8 * slot, STAGE_BYTES);
            bulk_copy(sbase + SMEM_W + slot * STAGE_BYTES,
                      wsrc0 + (size_t)(u + NSTAGE) * wstride, STAGE_BYTES,
                      mbF + 8 * slot);
        }
    }

    // ---- c-reduction via shared (reuse stage-0 buffer), fused fold scatter ----
    // no copies in flight after the loop (last refill consumed at u=15)
    float* red = (float*)smem;   // [16 s][144] = 9216 B
#pragma unroll
    for (int i = 0; i < 2; i++) {
        float4 pk = make_float4(acc[i][0], acc[i][1], acc[i][2], acc[i][3]);
        *(float4*)&red[(sgrp * 2 + i) * EE + lane * 4] = pk;
    }
    __syncthreads();

    // 16*36 = 576 (s, o*9+k) outputs; sum 4 c-slices each; fold-scatter
    for (int r = t; r < ST * 36; r += NTHREADS) {
        int sl = r / 36;
        int ok = r % 36;             // o*9 + k
        int o  = ok / 9, k = ok % 9;
        const float* rb = &red[sl * EE + ok];
        float val = rb[0] + rb[36] + rb[72] + rb[108];
        // fold: channel index ch = k*C + o decoded as (cf, fi, fj)
        int ch  = k * CC + o;
        int cf  = ch / 9;
        int rem = ch % 9;
        int fi  = rem / 3, fj = rem % 3;
        int s = bs0 + sl;
        int hh = s >> 5, w = s & 31;
        int y = hh + fi - 1, xx = w + fj - 1;
        if ((unsigned)y < 32u && (unsigned)xx < 32u)
            atomicAdd(&out[((v * CC + cf) * HH + y) * WW + xx], val);
    }
}

extern "C" void kernel_launch(void* const* d_in, const int* in_sizes, int n_in,
                              void* d_out, int out_size) {
    // identify inputs by element count (robust to ordering)
    const float *x = nullptr, *wt = nullptr, *cm = nullptr, *mk = nullptr;
    for (int i = 0; i < n_in; i++) {
        switch (in_sizes[i]) {
            case NN * CC * HH * WW:           x  = (const float*)d_in[i]; break; // 65536
            case NN * NN * SS * CC * CC * K2: wt = (const float*)d_in[i]; break; // 37748736
            case NN * NN * CC * CC:           cm = (const float*)d_in[i]; break; // 4096
            case NN * NN:                     mk = (const float*)d_in[i]; break; // 256
            default: break;
        }
    }
    float* out = (float*)d_out;

    cudaFuncSetAttribute(plastic_edges_kernel,
                         cudaFuncAttributeMaxDynamicSharedMemorySize, SMEM_TOTAL);

    cudaMemsetAsync(out, 0, (size_t)out_size * sizeof(float), 0);

    dim3 grid(SS / ST, NN);                  // (64, 16) = 1024 blocks
    plastic_edges_kernel<<<grid, NTHREADS, SMEM_TOTAL, 0>>>(x, wt, cm, mk, out);
}